// round 4
// baseline (speedup 1.0000x reference)
#include <cuda_runtime.h>
#include <math.h>

#define DD     32
#define DIMN   16
#define NTOT   4096
#define EPSV   1e-5f
#define LAM    0.1f
#define NSWEEP 6
#define WARPS_PER_BLK 8

typedef unsigned long long u64;

// ---------------- packed f32x2 helpers (Blackwell) --------------------------
__device__ __forceinline__ u64 pk(float x, float y) {
    u64 r; asm("mov.b64 %0,{%1,%2};" : "=l"(r) : "f"(x), "f"(y)); return r;
}
__device__ __forceinline__ float2 up(u64 a) {
    float2 v; asm("mov.b64 {%0,%1},%2;" : "=f"(v.x), "=f"(v.y) : "l"(a)); return v;
}
__device__ __forceinline__ u64 f2fma(u64 a, u64 b, u64 c) {
    u64 d; asm("fma.rn.f32x2 %0,%1,%2,%3;" : "=l"(d) : "l"(a), "l"(b), "l"(c)); return d;
}
__device__ __forceinline__ u64 f2mul(u64 a, u64 b) {
    u64 d; asm("mul.rn.f32x2 %0,%1,%2;" : "=l"(d) : "l"(a), "l"(b)); return d;
}
__device__ __forceinline__ u64 swp(u64 a) {
    float2 v = up(a); return pk(v.y, v.x);
}

// ---------------- scratch (device globals: no allocation allowed) -----------
__device__ float2 g_G[DIMN * DIMN];            // sum_d A_d A_d^H
__device__ float2 g_S[DD * DIMN * DIMN];       // A_d + A_d^H
__device__ float2 g_r[DD * DIMN];              // column sums of A_d
__device__ float2 g_r2[DD * DIMN];             // column sums of A_d @ A_d
__device__ double g_acc;
__device__ unsigned int g_cnt;

// ---------------- kernel -1: zero accumulators ------------------------------
__global__ void zero_kernel(float* __restrict__ out) {
    int t = threadIdx.x;
    g_G[t] = make_float2(0.f, 0.f);
    if (t == 0) { g_acc = 0.0; g_cnt = 0u; out[0] = 0.f; }
}

// ---------------- kernel 0: constants from A (one block per d) --------------
__global__ void precompute_kernel(const float* __restrict__ Ar,
                                  const float* __restrict__ Ai) {
    __shared__ float2 sr[DIMN];
    const int d = blockIdx.x;
    const int t = threadIdx.x;          // 256 threads, one per (i,j)
    const int i = t >> 4, j = t & 15;
    const float* ar = Ar + d * 256;
    const float* ai = Ai + d * 256;

    // S_d = A_d + A_d^H
    float arij = ar[i * 16 + j], aiij = ai[i * 16 + j];
    float arji = ar[j * 16 + i], aiji = ai[j * 16 + i];
    g_S[d * 256 + t] = make_float2(arij + arji, aiij - aiji);

    // partial G: G[i][j] += sum_k A[i,k] conj(A[j,k])
    float gx = 0.f, gy = 0.f;
    #pragma unroll
    for (int k = 0; k < 16; k++) {
        float axr = ar[i * 16 + k], axi = ai[i * 16 + k];
        float bxr = ar[j * 16 + k], bxi = ai[j * 16 + k];
        gx += axr * bxr + axi * bxi;
        gy += axi * bxr - axr * bxi;
    }
    atomicAdd(&g_G[t].x, gx);
    atomicAdd(&g_G[t].y, gy);

    // r_d[j] = sum_i A_d[i,j]
    if (t < 16) {
        float2 s = make_float2(0.f, 0.f);
        #pragma unroll
        for (int ii = 0; ii < 16; ii++) {
            s.x += ar[ii * 16 + t];
            s.y += ai[ii * 16 + t];
        }
        sr[t] = s;
        g_r[d * 16 + t] = s;
    }
    __syncthreads();
    // r2_d[j] = sum_k r_d[k] * A_d[k,j]
    if (t < 16) {
        float2 s = make_float2(0.f, 0.f);
        #pragma unroll
        for (int k = 0; k < 16; k++) {
            float2 rk = sr[k];
            float axr = ar[k * 16 + t], axi = ai[k * 16 + t];
            s.x += rk.x * axr - rk.y * axi;
            s.y += rk.x * axi + rk.y * axr;
        }
        g_r2[d * 16 + t] = s;
    }
}

// ---------------- kernel 1: build H, one-sided Jacobi (f32x2 packed) --------
__global__ void __launch_bounds__(WARPS_PER_BLK * 32)
solve_kernel(const float* __restrict__ X, float* __restrict__ out) {
    __shared__ float2 sH[WARPS_PER_BLK][DIMN * 17];   // build/transpose buffer
    __shared__ float2 spsi[WARPS_PER_BLK][DIMN];

    const int w    = threadIdx.x >> 5;
    const int lane = threadIdx.x & 31;
    const int n    = blockIdx.x * WARPS_PER_BLK + w;
    const unsigned FULL = 0xffffffffu;
    const u64* S64 = reinterpret_cast<const u64*>(g_S);
    const u64* G64 = reinterpret_cast<const u64*>(g_G);

    float2* H = sH[w];

    // ---- load x_n, ||x||^2 ----
    float x = X[n * DD + lane];
    float sx2 = x * x;
    #pragma unroll
    for (int o = 16; o > 0; o >>= 1) sx2 += __shfl_xor_sync(FULL, sx2, o);

    // ---- H = 0.5*G - 0.5*sum_d x_d S_d + (eps + 0.5*||x||^2) I ----
    {
        const u64 HALF2 = pk(0.5f, 0.5f);
        u64 acc[8];
        #pragma unroll
        for (int m = 0; m < 8; m++)
            acc[m] = f2mul(HALF2, G64[m * 32 + lane]);
        #pragma unroll
        for (int d = 0; d < DD; d++) {
            float h = -0.5f * __shfl_sync(FULL, x, d);
            u64 NH2 = pk(h, h);
            #pragma unroll
            for (int m = 0; m < 8; m++)
                acc[m] = f2fma(NH2, S64[d * 256 + m * 32 + lane], acc[m]);
        }
        #pragma unroll
        for (int m = 0; m < 8; m++) {
            int e = m * 32 + lane;
            int i = e >> 4, j = e & 15;
            float2 a = up(acc[m]);
            if (i == j) a.x += EPSV + 0.5f * sx2;
            H[i * 17 + j] = a;
        }
    }
    __syncwarp();

    // ---- register layout: group g = lane>>2 holds columns (2g, 2g+1);
    //      lane rl = lane&3 holds rows {4r+rl}; packed (re,im) in u64 ----
    const int g  = lane >> 2;
    const int rl = lane & 3;

    u64 Tp[4], Bp[4];
    #pragma unroll
    for (int r = 0; r < 4; r++) {
        float2 t0 = H[(r * 4 + rl) * 17 + 2 * g];
        float2 b0 = H[(r * 4 + rl) * 17 + 2 * g + 1];
        Tp[r] = pk(t0.x, t0.y);
        Bp[r] = pk(b0.x, b0.y);
    }

    // ---- one-sided Jacobi: 15 rounds/sweep (round-robin), registers only ----
    for (int it = 0; it < NSWEEP * 15; it++) {
        // Gram of the pair this group holds (packed accumulators)
        u64 TT = 0, BB = 0, P1 = 0, P2 = 0;
        u64 Bs[4];
        #pragma unroll
        for (int r = 0; r < 4; r++) {
            Bs[r] = swp(Bp[r]);
            TT = f2fma(Tp[r], Tp[r], TT);
            BB = f2fma(Bp[r], Bp[r], BB);
            P1 = f2fma(Tp[r], Bp[r], P1);
            P2 = f2fma(Tp[r], Bs[r], P2);
        }
        float2 tt = up(TT), bb = up(BB), p1 = up(P1), p2 = up(P2);
        float df = (bb.x + bb.y) - (tt.x + tt.y);   // |B|^2 - |T|^2
        float bx = p1.x + p1.y;                     // Re(conj(T).B)
        float by = p2.x - p2.y;                     // Im(conj(T).B)
        #pragma unroll
        for (int o = 1; o <= 2; o <<= 1) {
            df += __shfl_xor_sync(FULL, df, o);
            bx += __shfl_xor_sync(FULL, bx, o);
            by += __shfl_xor_sync(FULL, by, o);
        }

        // rotation params (same validated formulas)
        float ab2 = bx * bx + by * by;
        float c = 1.f, wx = 0.f, wy = 0.f;
        if (ab2 > 1e-28f) {
            float ab  = sqrtf(ab2);
            float tau = df / (2.f * ab);
            float ttv = ((tau >= 0.f) ? 1.f : -1.f) /
                        (fabsf(tau) + sqrtf(tau * tau + 1.f));
            c = rsqrtf(ttv * ttv + 1.f);
            float s   = ttv * c;
            float inv = s / ab;
            wx = bx * inv; wy = by * inv;
        }
        const u64 C2   = pk(c, c);
        const u64 WX2  = pk(wx, wx);
        const u64 NWX2 = pk(-wx, -wx);
        const u64 NWY  = pk(-wy, wy);

        // column update (6 packed ops/row) + fused round-robin permutation
        #pragma unroll
        for (int r = 0; r < 4; r++) {
            u64 Ts = swp(Tp[r]);
            u64 nT = f2fma(C2, Tp[r], f2fma(NWX2, Bp[r], f2mul(NWY, Bs[r])));
            u64 nB = f2fma(C2, Bp[r], f2fma(WX2, Tp[r], f2mul(NWY, Ts)));

            // merged shuffle: source lane pre-selects what downstream needs
            u64 sel = (g == 0) ? nB : nT;
            float2 sf = up(sel), bf = up(nB);
            float upx = __shfl_sync(FULL, sf.x, lane - 4);
            float upy = __shfl_sync(FULL, sf.y, lane - 4);
            float dnx = __shfl_sync(FULL, bf.x, lane + 4);
            float dny = __shfl_sync(FULL, bf.y, lane + 4);

            Tp[r] = (g == 0) ? nT : pk(upx, upy);
            Bp[r] = (g == 7) ? nT : pk(dnx, dny);
        }
    }

    // ---- column norms, pick minimum (= min eigenvalue's column) ----
    u64 NT2 = 0, NB2 = 0;
    #pragma unroll
    for (int r = 0; r < 4; r++) {
        NT2 = f2fma(Tp[r], Tp[r], NT2);
        NB2 = f2fma(Bp[r], Bp[r], NB2);
    }
    float2 ntv = up(NT2), nbv = up(NB2);
    float nT = ntv.x + ntv.y, nB = nbv.x + nbv.y;
    #pragma unroll
    for (int o = 1; o <= 2; o <<= 1) {
        nT += __shfl_xor_sync(FULL, nT, o);
        nB += __shfl_xor_sync(FULL, nB, o);
    }
    float v; int tag;
    if (nB < nT) { v = nB; tag = 2 * g + 1; } else { v = nT; tag = 2 * g; }
    #pragma unroll
    for (int o = 4; o <= 16; o <<= 1) {
        float ov = __shfl_xor_sync(FULL, v, o);
        int   ot = __shfl_xor_sync(FULL, tag, o);
        if (ov < v || (ov == v && ot < tag)) { v = ov; tag = ot; }
    }

    // psi = winning column / ||column||   (phase normalization cancels)
    float sc = rsqrtf(v);
    if (g == (tag >> 1)) {
        #pragma unroll
        for (int r = 0; r < 4; r++) {
            float2 cv = up((tag & 1) ? Bp[r] : Tp[r]);
            spsi[w][r * 4 + rl] = make_float2(cv.x * sc, cv.y * sc);
        }
    }
    __syncwarp();

    // t = sum_k psi_k
    float2 psi = (lane < 16) ? spsi[w][lane] : make_float2(0.f, 0.f);
    float2 tsum = psi;
    #pragma unroll
    for (int o = 16; o > 0; o >>= 1) {
        tsum.x += __shfl_xor_sync(FULL, tsum.x, o);
        tsum.y += __shfl_xor_sync(FULL, tsum.y, o);
    }

    // lane == d : u_d = r_d . psi ; v_d = r2_d . psi  (packed complex dots)
    const u64* R64  = reinterpret_cast<const u64*>(g_r);
    const u64* R264 = reinterpret_cast<const u64*>(g_r2);
    u64 UP = 0, UQ = 0, VP = 0, VQ = 0;
    #pragma unroll
    for (int j2 = 0; j2 < 16; j2++) {
        float2 pj = spsi[w][j2];
        u64 PJ  = pk(pj.x, pj.y);
        u64 PJS = pk(pj.y, pj.x);
        u64 rr  = R64[lane * 16 + j2];
        u64 r2  = R264[lane * 16 + j2];
        UP = f2fma(rr, PJ, UP);     // (Σ rx*px, Σ ry*py)
        UQ = f2fma(rr, PJS, UQ);    // (Σ rx*py, Σ ry*px)
        VP = f2fma(r2, PJ, VP);
        VQ = f2fma(r2, PJS, VQ);
    }
    float2 upv = up(UP), uqv = up(UQ), vpv = up(VP), vqv = up(VQ);
    float ux = upv.x - upv.y, uy = uqv.x + uqv.y;
    float vx = vpv.x - vpv.y, vy = vqv.x + vqv.y;

    float pos = ux * tsum.x + uy * tsum.y;   // Re(u * conj(t))
    float e2  = vx * tsum.x + vy * tsum.y;
    float dlt = pos - x;
    float contrib = dlt * dlt + LAM * (e2 - pos * pos);

    #pragma unroll
    for (int o = 16; o > 0; o >>= 1)
        contrib += __shfl_xor_sync(FULL, contrib, o);

    if (lane == 0) {
        atomicAdd(&g_acc, (double)contrib);
        __threadfence();
        unsigned int t = atomicAdd(&g_cnt, 1u);
        if (t == (unsigned)(NTOT - 1)) {
            double total = atomicAdd(&g_acc, 0.0);   // coherent read of final sum
            out[0] = (float)(total * (1.0 / (double)NTOT));
        }
    }
}

extern "C" void kernel_launch(void* const* d_in, const int* in_sizes, int n_in,
                              void* d_out, int out_size) {
    const float* Ar = (const float*)d_in[0];
    const float* Ai = (const float*)d_in[1];
    const float* X  = (const float*)d_in[2];
    float* out = (float*)d_out;

    zero_kernel<<<1, 256>>>(out);
    precompute_kernel<<<DD, 256>>>(Ar, Ai);
    solve_kernel<<<NTOT / WARPS_PER_BLK, WARPS_PER_BLK * 32>>>(X, out);
}